// round 5
// baseline (speedup 1.0000x reference)
#include <cuda_runtime.h>
#include <cstdint>

#define N     8192
#define FIN   512
#define FO    64
#define NW    256             // mask words per row
#define NEG_BIG (-9e15f)
#define INVN  (1.0f/8192.0f)
#define KS    4               // K-splits in k_main

// ---- scratch ----
__device__ float    g_Wh[N*FO];
__device__ float    g_Wh1[N];
__device__ float    g_Wh2[N];
__device__ float    g_B[N];           // exp(wh2)
__device__ float    g_D[N];           // exp(0.2*wh2)
__device__ float    g_add[N];
__device__ float    g_cpm[N], g_ncm[N], g_cpn[N], g_ncn[N];
__device__ unsigned g_mask[N*NW];
__device__ unsigned g_maskn[N*NW];
__device__ float    g_hp[N*FO];

__device__ __forceinline__ uint32_t tf32bits(float x) {
    uint32_t r; asm("cvt.rna.tf32.f32 %0, %1;" : "=r"(r) : "f"(x)); return r;
}
__device__ __forceinline__ void mma_tf32(float* d,
        uint32_t a0, uint32_t a1, uint32_t a2, uint32_t a3,
        uint32_t b0, uint32_t b1) {
    asm volatile("mma.sync.aligned.m16n8k8.row.col.f32.tf32.tf32.f32 "
        "{%0,%1,%2,%3}, {%4,%5,%6,%7}, {%8,%9}, {%0,%1,%2,%3};"
        : "+f"(d[0]), "+f"(d[1]), "+f"(d[2]), "+f"(d[3])
        : "r"(a0), "r"(a1), "r"(a2), "r"(a3), "r"(b0), "r"(b1));
}

// ============================================================
// Kernel 1: Wh = h @ W ; Wh1 ; Wh2
// ============================================================
__global__ void k_gemm1(const float* __restrict__ h,
                        const float* __restrict__ W,
                        const float* __restrict__ a) {
    __shared__ float a_s[2*FO];
    __shared__ float r1[8][2], r2[8][2];
    int t = threadIdx.x;
    if (t < 2*FO) a_s[t] = a[t];
    int row = t >> 6;
    int f   = t & 63;
    int i   = blockIdx.x * 8 + row;
    __syncthreads();

    const float* hrow = h + (size_t)i * FIN;
    float acc = 0.f;
    #pragma unroll 4
    for (int k = 0; k < FIN; k += 4) {
        float4 hv = *reinterpret_cast<const float4*>(hrow + k);
        acc += hv.x * W[(k+0)*FO + f];
        acc += hv.y * W[(k+1)*FO + f];
        acc += hv.z * W[(k+2)*FO + f];
        acc += hv.w * W[(k+3)*FO + f];
    }
    g_Wh[(size_t)i*FO + f] = acc;

    float p1 = acc * a_s[f];
    float p2 = acc * a_s[FO + f];
    #pragma unroll
    for (int off = 16; off; off >>= 1) {
        p1 += __shfl_down_sync(0xffffffffu, p1, off);
        p2 += __shfl_down_sync(0xffffffffu, p2, off);
    }
    int w = t >> 5;
    if ((t & 31) == 0) { r1[w>>1][w&1] = p1; r2[w>>1][w&1] = p2; }
    __syncthreads();
    if (t < 8) {
        g_Wh1[blockIdx.x*8 + t] = r1[t][0] + r1[t][1];
        g_Wh2[blockIdx.x*8 + t] = r2[t][0] + r2[t][1];
    }
}

// ============================================================
// Kernel 1b: B[j] = exp(wh2_j), D[j] = exp(0.2 wh2_j)
// ============================================================
__global__ void k_prep() {
    int tid = blockIdx.x * 256 + threadIdx.x;
    float w2a = g_Wh2[2*tid], w2b = g_Wh2[2*tid+1];
    g_B[2*tid]   = expf(w2a);
    g_B[2*tid+1] = expf(w2b);
    g_D[2*tid]   = expf(0.2f * w2a);
    g_D[2*tid+1] = expf(0.2f * w2b);
}

// ============================================================
// Kernel 2: one adj pass -> bitmasks + per-row softmax coefs
// 4-way independent accumulator chains for ILP
// ============================================================
__global__ void k_stats(const int* __restrict__ adj,
                        const int* __restrict__ adjn) {
    int tid = blockIdx.x * 256 + threadIdx.x;
    g_hp[2*tid]     = 0.f;
    g_hp[2*tid + 1] = 0.f;

    int lane = threadIdx.x & 31;
    int i    = blockIdx.x * 8 + (threadIdx.x >> 5);
    float wh1 = g_Wh1[i];
    float thr = -wh1;
    const int* arow = adj  + (size_t)i * N;
    const int* nrow = adjn + (size_t)i * N;

    float Mm0 = NEG_BIG, Mm1 = NEG_BIG, Mm2 = NEG_BIG, Mm3 = NEG_BIG;
    float Mn0 = NEG_BIG, Mn1 = NEG_BIG, Mn2 = NEG_BIG, Mn3 = NEG_BIG;
    float Smp0 = 0.f, Smp1 = 0.f, Smn0 = 0.f, Smn1 = 0.f;
    float Snp0 = 0.f, Snp1 = 0.f, Snn0 = 0.f, Snn1 = 0.f;

    #pragma unroll 2
    for (int k = 0; k < N/128; k++) {
        int jb = k*128 + lane*4;
        int4   av = *reinterpret_cast<const int4*>(&arow[jb]);
        int4   nv = *reinterpret_cast<const int4*>(&nrow[jb]);
        float4 w2 = *reinterpret_cast<const float4*>(&g_Wh2[jb]);
        float4 Bv = *reinterpret_cast<const float4*>(&g_B[jb]);
        float4 Dv = *reinterpret_cast<const float4*>(&g_D[jb]);

        unsigned nm = 0, nn = 0;
        {
            bool bm = av.x > 0, bn = nv.x > 0, p = w2.x > thr;
            if (bm) { Mm0 = fmaxf(Mm0, w2.x); if (p) Smp0 += Bv.x; else Smn0 += Dv.x; nm |= 1u; }
            if (bn) { Mn0 = fmaxf(Mn0, w2.x); if (p) Snp0 += Bv.x; else Snn0 += Dv.x; nn |= 1u; }
        }
        {
            bool bm = av.y > 0, bn = nv.y > 0, p = w2.y > thr;
            if (bm) { Mm1 = fmaxf(Mm1, w2.y); if (p) Smp1 += Bv.y; else Smn1 += Dv.y; nm |= 2u; }
            if (bn) { Mn1 = fmaxf(Mn1, w2.y); if (p) Snp1 += Bv.y; else Snn1 += Dv.y; nn |= 2u; }
        }
        {
            bool bm = av.z > 0, bn = nv.z > 0, p = w2.z > thr;
            if (bm) { Mm2 = fmaxf(Mm2, w2.z); if (p) Smp0 += Bv.z; else Smn0 += Dv.z; nm |= 4u; }
            if (bn) { Mn2 = fmaxf(Mn2, w2.z); if (p) Snp0 += Bv.z; else Snn0 += Dv.z; nn |= 4u; }
        }
        {
            bool bm = av.w > 0, bn = nv.w > 0, p = w2.w > thr;
            if (bm) { Mm3 = fmaxf(Mm3, w2.w); if (p) Smp1 += Bv.w; else Smn1 += Dv.w; nm |= 8u; }
            if (bn) { Mn3 = fmaxf(Mn3, w2.w); if (p) Snp1 += Bv.w; else Snn1 += Dv.w; nn |= 8u; }
        }
        unsigned vm = nm << ((lane & 7) * 4);
        unsigned vn = nn << ((lane & 7) * 4);
        vm |= __shfl_xor_sync(0xffffffffu, vm, 1);
        vn |= __shfl_xor_sync(0xffffffffu, vn, 1);
        vm |= __shfl_xor_sync(0xffffffffu, vm, 2);
        vn |= __shfl_xor_sync(0xffffffffu, vn, 2);
        vm |= __shfl_xor_sync(0xffffffffu, vm, 4);
        vn |= __shfl_xor_sync(0xffffffffu, vn, 4);
        if ((lane & 7) == 0) {
            g_mask [(size_t)i*NW + k*4 + (lane>>3)] = vm;
            g_maskn[(size_t)i*NW + k*4 + (lane>>3)] = vn;
        }
    }
    float Mm = fmaxf(fmaxf(Mm0, Mm1), fmaxf(Mm2, Mm3));
    float Mn = fmaxf(fmaxf(Mn0, Mn1), fmaxf(Mn2, Mn3));
    float Smp = Smp0 + Smp1, Smn = Smn0 + Smn1;
    float Snp = Snp0 + Snp1, Snn = Snn0 + Snn1;

    #pragma unroll
    for (int off = 16; off; off >>= 1) {
        Mm  = fmaxf(Mm, __shfl_xor_sync(0xffffffffu, Mm, off));
        Mn  = fmaxf(Mn, __shfl_xor_sync(0xffffffffu, Mn, off));
        Smp += __shfl_xor_sync(0xffffffffu, Smp, off);
        Smn += __shfl_xor_sync(0xffffffffu, Smn, off);
        Snp += __shfl_xor_sync(0xffffffffu, Snp, off);
        Snn += __shfl_xor_sync(0xffffffffu, Snn, off);
    }
    if (lane == 0) {
        bool hasm = Mm > 0.5f*NEG_BIG, hasn = Mn > 0.5f*NEG_BIG;
        float Mu = fmaxf(Mm, Mn);
        float x  = wh1 + Mu;
        float base = (hasm || hasn) ? (x > 0.f ? x : 0.2f * x) : 0.f;
        float ep = expf(wh1 - base);
        float en = expf(0.2f * wh1 - base);
        float dm = ep * Smp + en * Smn;
        float dn = ep * Snp + en * Snn;
        float km = (dm > 0.f) ? 1.f / dm : 0.f;
        float kn = (dn > 0.f) ? 1.f / dn : 0.f;
        g_add[i] = ((dm > 0.f) ? 0.f : INVN) + ((dn > 0.f) ? 0.f : INVN);
        g_cpm[i] = ep * km;  g_ncm[i] = en * km;
        g_cpn[i] = ep * kn;  g_ncn[i] = en * kn;
    }
}

// ============================================================
// Kernel 3: fused attention + tf32 mma.sync (attn @ Wh)
// grid (KS, N/64); 128 thr = 4 warps x 16 rows = 64 rows/CTA
// attention staged in smem -> coalesced float4 stores
// ============================================================
__device__ __forceinline__ float attn_val(float w2, float Bj, float Dj,
        float thr, float add, float cpm, float ncm, float cpn, float ncn,
        unsigned mb, unsigned nb) {
    bool  p  = w2 > thr;
    float E  = p ? Bj : Dj;
    float cm = p ? cpm : ncm;
    float cn = p ? cpn : ncn;
    float wg = ((mb & 1u) ? cm : 0.f) + ((nb & 1u) ? cn : 0.f);
    return fmaf(E, wg, add);
}

__global__ void __launch_bounds__(128, 4) k_main(float* __restrict__ attn) {
    __shared__ uint32_t whs[64*72];            // tf32 Wh tile, padded (18.4 KB)
    __shared__ float    at_s[64*68];           // attention tile [row][j] (17.4 KB)
    __shared__ float    Bs[64], Ds[64], w2s[64];

    int t = threadIdx.x, w = t >> 5, lane = t & 31;
    int g = lane >> 2, c = lane & 3;
    int i0 = blockIdx.y * 64;
    int rel0 = w*16 + g, rel1 = rel0 + 8;
    int r0 = i0 + rel0, r1 = i0 + rel1;

    float thr0 = -g_Wh1[r0],  thr1 = -g_Wh1[r1];
    float add0 = g_add[r0],   add1 = g_add[r1];
    float cpm0 = g_cpm[r0], ncm0 = g_ncm[r0], cpn0 = g_cpn[r0], ncn0 = g_ncn[r0];
    float cpm1 = g_cpm[r1], ncm1 = g_ncm[r1], cpn1 = g_cpn[r1], ncn1 = g_ncn[r1];

    float acc[8][4];
    #pragma unroll
    for (int nt = 0; nt < 8; nt++)
        #pragma unroll
        for (int q = 0; q < 4; q++) acc[nt][q] = 0.f;

    int jcta = blockIdx.x * (N/KS);

    for (int tt = 0; tt < (N/KS)/64; tt++) {
        int j0 = jcta + tt*64;
        __syncthreads();
        // stage Wh tile (64 j x 64 f) as tf32, row pad 72
        #pragma unroll
        for (int q = 0; q < 8; q++) {
            int idx = t + 128*q;
            int r = idx >> 4, c4 = (idx & 15) * 4;
            float4 v = *reinterpret_cast<const float4*>(&g_Wh[(size_t)(j0+r)*FO + c4]);
            uint32_t* p = &whs[r*72 + c4];
            p[0] = tf32bits(v.x); p[1] = tf32bits(v.y);
            p[2] = tf32bits(v.z); p[3] = tf32bits(v.w);
        }
        if (t < 64) { Bs[t] = g_B[j0+t]; Ds[t] = g_D[j0+t]; w2s[t] = g_Wh2[j0+t]; }
        __syncthreads();

        int wb = j0 >> 5;
        uint2 mw0 = *reinterpret_cast<const uint2*>(&g_mask [(size_t)r0*NW + wb]);
        uint2 nw0 = *reinterpret_cast<const uint2*>(&g_maskn[(size_t)r0*NW + wb]);
        uint2 mw1 = *reinterpret_cast<const uint2*>(&g_mask [(size_t)r1*NW + wb]);
        uint2 nw1 = *reinterpret_cast<const uint2*>(&g_maskn[(size_t)r1*NW + wb]);

        #pragma unroll
        for (int kk = 0; kk < 8; kk++) {
            int jA = kk*8 + c, jB = jA + 4;
            float BA = Bs[jA], DA = Ds[jA], wA = w2s[jA];
            float BB = Bs[jB], DB = Ds[jB], wB = w2s[jB];
            unsigned m0 = (kk < 4) ? mw0.x : mw0.y;
            unsigned n0 = (kk < 4) ? nw0.x : nw0.y;
            unsigned m1 = (kk < 4) ? mw1.x : mw1.y;
            unsigned n1 = (kk < 4) ? nw1.x : nw1.y;
            int sA = (kk & 3)*8 + c, sB = sA + 4;

            float v00 = attn_val(wA, BA, DA, thr0, add0, cpm0, ncm0, cpn0, ncn0, m0>>sA, n0>>sA);
            float v10 = attn_val(wA, BA, DA, thr1, add1, cpm1, ncm1, cpn1, ncn1, m1>>sA, n1>>sA);
            float v01 = attn_val(wB, BB, DB, thr0, add0, cpm0, ncm0, cpn0, ncn0, m0>>sB, n0>>sB);
            float v11 = attn_val(wB, BB, DB, thr1, add1, cpm1, ncm1, cpn1, ncn1, m1>>sB, n1>>sB);

            // conflict-free STS (banks 4g+c+8kk all distinct within warp)
            at_s[rel0*68 + jA] = v00;  at_s[rel0*68 + jB] = v01;
            at_s[rel1*68 + jA] = v10;  at_s[rel1*68 + jB] = v11;

            uint32_t a0 = tf32bits(v00), a1 = tf32bits(v10);
            uint32_t a2 = tf32bits(v01), a3 = tf32bits(v11);

            int rowA = jA*72, rowB = jB*72;
            #pragma unroll
            for (int nt = 0; nt < 8; nt++) {
                uint32_t b0 = whs[rowA + nt*8 + g];
                uint32_t b1 = whs[rowB + nt*8 + g];
                mma_tf32(acc[nt], a0, a1, a2, a3, b0, b1);
            }
        }
        __syncthreads();

        // coalesced copy-out: 64x64 tile = 1024 float4, 8 per thread
        #pragma unroll
        for (int q = 0; q < 8; q++) {
            int idx = t + 128*q;
            int row = idx >> 4, c4 = (idx & 15) * 4;
            float4 v = *reinterpret_cast<const float4*>(&at_s[row*68 + c4]);
            *reinterpret_cast<float4*>(&attn[(size_t)(i0+row)*N + j0 + c4]) = v;
        }
    }

    #pragma unroll
    for (int nt = 0; nt < 8; nt++) {
        atomicAdd(&g_hp[(size_t)r0*FO + nt*8 + 2*c    ], acc[nt][0]);
        atomicAdd(&g_hp[(size_t)r0*FO + nt*8 + 2*c + 1], acc[nt][1]);
        atomicAdd(&g_hp[(size_t)r1*FO + nt*8 + 2*c    ], acc[nt][2]);
        atomicAdd(&g_hp[(size_t)r1*FO + nt*8 + 2*c + 1], acc[nt][3]);
    }
}

// ============================================================
// Kernel 4: out = elu(h_prime)
// ============================================================
__global__ void k_elu(float* __restrict__ out) {
    int tid = blockIdx.x * 256 + threadIdx.x;
    float x = g_hp[tid];
    out[tid] = x > 0.f ? x : expm1f(x);
}

// ============================================================
extern "C" void kernel_launch(void* const* d_in, const int* in_sizes, int n_in,
                              void* d_out, int out_size) {
    const float* h    = (const float*)d_in[0];
    const float* W    = (const float*)d_in[1];
    const float* a    = (const float*)d_in[2];
    const int*   adj  = (const int*)d_in[3];
    const int*   adjn = (const int*)d_in[4];

    float* out  = (float*)d_out;
    float* attn = out + (size_t)N * FO;

    k_gemm1<<<N/8, 512>>>(h, W, a);
    k_prep<<<N/512, 256>>>();
    k_stats<<<N/8, 256>>>(adj, adjn);
    k_main<<<dim3(KS, N/64), 128>>>(attn);
    k_elu<<<(N*FO)/256, 256>>>(out);
}